// round 1
// baseline (speedup 1.0000x reference)
#include <cuda_runtime.h>
#include <cuda_bf16.h>
#include <math.h>

// ---------------------------------------------------------------------------
// VariationalLinear fused kernel (sm_100a)
//   output(256,4096) = x(256,4096) @ W^T + b,  W = mu + softplus(rho)*eps_w
//   kl = sum over weights of log(ps/sigma) + (sigma^2+(mu-pm)^2)/(2 ps^2) - 0.5
//
// Strategy: stream the 5 weight-space arrays exactly once (335 MB, HBM-bound),
// generate W on the fly into SMEM (tf32-rounded), tf32 mma.sync GEMM against a
// cp.async-staged x tile. Grid: 64 N-tiles x 2 K-halves = 128 CTAs.
// Partial outputs combined with atomicAdd into zeroed d_out.
// ---------------------------------------------------------------------------

#define BATCH   256
#define IN_F    4096
#define OUT_F   4096
#define NT      64          // out-features per CTA
#define KSPLIT  2
#define KHALF   (IN_F / KSPLIT)   // 2048
#define KC      32          // K chunk per pipeline stage
#define NCHUNK  (KHALF / KC)      // 64
#define XSTRIDE 36          // padded row stride (floats) -> conflict-free frag loads
#define THREADS 256

#define XS_STAGE (BATCH * XSTRIDE)   // 9216 floats
#define WS_STAGE (NT * XSTRIDE)      // 2304 floats
#define SMEM_FLOATS (2 * XS_STAGE + 2 * WS_STAGE)
#define SMEM_BYTES  (SMEM_FLOATS * 4)   // 92160

__device__ __align__(16) float g_x_tf32[BATCH * IN_F];

__device__ __forceinline__ unsigned cvt_tf32(float x) {
    unsigned r;
    asm volatile("cvt.rna.tf32.f32 %0, %1;" : "=r"(r) : "f"(x));
    return r;
}

__device__ __forceinline__ void cp_async16(void* smem_dst, const void* gsrc) {
    unsigned saddr = (unsigned)__cvta_generic_to_shared(smem_dst);
    asm volatile("cp.async.cg.shared.global [%0], [%1], 16;"
                 :: "r"(saddr), "l"(gsrc));
}

__device__ __forceinline__ void mma_tf32(float* c, const unsigned* a,
                                         unsigned b0, unsigned b1) {
    asm volatile(
        "mma.sync.aligned.m16n8k8.row.col.f32.tf32.tf32.f32 "
        "{%0,%1,%2,%3}, {%4,%5,%6,%7}, {%8,%9}, {%0,%1,%2,%3};"
        : "+f"(c[0]), "+f"(c[1]), "+f"(c[2]), "+f"(c[3])
        : "r"(a[0]), "r"(a[1]), "r"(a[2]), "r"(a[3]), "r"(b0), "r"(b1));
}

__device__ __forceinline__ float softplus_fast(float r) {
    // rho ~ -2.25 here; guard large args anyway
    return (r > 15.f) ? r : __logf(1.f + __expf(r));
}

// ---------------------------------------------------------------------------
// Prep kernel: zero d_out (atomics accumulate into it) and pre-round x to tf32
// ---------------------------------------------------------------------------
__global__ void vl_prep(const float* __restrict__ x, float* __restrict__ out,
                        int out_size) {
    int i = blockIdx.x * blockDim.x + threadIdx.x;
    if (i < out_size) out[i] = 0.f;
    if (i < BATCH * IN_F) g_x_tf32[i] = __uint_as_float(cvt_tf32(x[i]));
}

// ---------------------------------------------------------------------------
// Main fused kernel
// ---------------------------------------------------------------------------
__global__ void __launch_bounds__(THREADS)
vl_main(const float* __restrict__ mu, const float* __restrict__ rho,
        const float* __restrict__ epsw, const float* __restrict__ pmu,
        const float* __restrict__ psig, const float* __restrict__ bmu,
        const float* __restrict__ brho, const float* __restrict__ epsb,
        float* __restrict__ out, float* __restrict__ klout) {
    extern __shared__ float sm[];
    float* Xs = sm;                      // [2][BATCH][XSTRIDE]
    float* Ws = sm + 2 * XS_STAGE;       // [2][NT][XSTRIDE]
    __shared__ float bias_s[NT];
    __shared__ float klred[8];

    const int tid  = threadIdx.x;
    const int warp = tid >> 5;
    const int lane = tid & 31;
    const int g    = lane >> 2;          // 0..7
    const int t    = lane & 3;           // 0..3

    const int ntile = blockIdx.x >> 1;
    const int khalf = blockIdx.x & 1;
    const int n0    = ntile * NT;
    const int kbase = khalf * KHALF;

    // accumulators: warp owns M rows [warp*32, warp*32+32), all 64 N cols
    float acc[2][8][4];
#pragma unroll
    for (int mt = 0; mt < 2; mt++)
#pragma unroll
        for (int nt = 0; nt < 8; nt++)
#pragma unroll
            for (int i = 0; i < 4; i++) acc[mt][nt][i] = 0.f;

    float klsum = 0.f;

    // weight-slab staging offsets: thread handles 2 float4 per stream per chunk
    int row_j[2], seg_j[2];
    long gofs[2];
    int  sofs[2];
#pragma unroll
    for (int j = 0; j < 2; j++) {
        int idx4 = tid * 2 + j;          // 0..511 over 64 rows x 8 segs
        row_j[j] = idx4 >> 3;
        seg_j[j] = idx4 & 7;
        gofs[j]  = (long)(n0 + row_j[j]) * IN_F + seg_j[j] * 4;
        sofs[j]  = row_j[j] * XSTRIDE + seg_j[j] * 4;
    }

    float4 wmu[2], wrho[2], weps[2], wpm[2], wps[2];

    auto loadW = [&](int k0) {
#pragma unroll
        for (int j = 0; j < 2; j++) {
            long o = gofs[j] + k0;
            wmu[j]  = *reinterpret_cast<const float4*>(mu   + o);
            wrho[j] = *reinterpret_cast<const float4*>(rho  + o);
            weps[j] = *reinterpret_cast<const float4*>(epsw + o);
            wpm[j]  = *reinterpret_cast<const float4*>(pmu  + o);
            wps[j]  = *reinterpret_cast<const float4*>(psig + o);
        }
    };

    auto loadX = [&](int stage, int k0) {
        float* dst = Xs + stage * XS_STAGE;
#pragma unroll
        for (int i = 0; i < 8; i++) {
            int fid = tid + THREADS * i;     // 0..2047
            int r   = fid >> 3;
            int s   = fid & 7;
            cp_async16(dst + r * XSTRIDE + s * 4,
                       g_x_tf32 + (long)r * IN_F + k0 + s * 4);
        }
    };

    // prologue: stage chunk 0
    loadW(kbase);
    loadX(0, kbase);
    asm volatile("cp.async.commit_group;");

    for (int c = 0; c < NCHUNK; c++) {
        const int cur = c & 1;
        const int nxt = cur ^ 1;
        float* Xc = Xs + cur * XS_STAGE;
        float* Wc = Ws + cur * WS_STAGE;

        // ---- generate W tile (tf32-rounded) + KL from staged registers ----
#pragma unroll
        for (int j = 0; j < 2; j++) {
            float4 m4 = wmu[j], r4 = wrho[j], e4 = weps[j];
            float4 p4 = wpm[j], s4 = wps[j];
            float wv[4];
            {
                const float mv[4] = {m4.x, m4.y, m4.z, m4.w};
                const float rv[4] = {r4.x, r4.y, r4.z, r4.w};
                const float ev[4] = {e4.x, e4.y, e4.z, e4.w};
                const float pv[4] = {p4.x, p4.y, p4.z, p4.w};
                const float sv[4] = {s4.x, s4.y, s4.z, s4.w};
#pragma unroll
                for (int q = 0; q < 4; q++) {
                    float sg = softplus_fast(rv[q]);
                    float w  = fmaf(sg, ev[q], mv[q]);
                    wv[q] = __uint_as_float(cvt_tf32(w));
                    float d   = mv[q] - pv[q];
                    float ps2 = sv[q] * sv[q];
                    klsum += __logf(sv[q]) - __logf(sg)
                           + __fdividef(0.5f * fmaf(sg, sg, d * d), ps2)
                           - 0.5f;
                }
            }
            float4 wo = make_float4(wv[0], wv[1], wv[2], wv[3]);
            *reinterpret_cast<float4*>(Wc + sofs[j]) = wo;
        }

        // ---- prefetch next chunk (overlaps with MMA below) ----
        if (c + 1 < NCHUNK) {
            int k1 = kbase + (c + 1) * KC;
            loadX(nxt, k1);
            asm volatile("cp.async.commit_group;");
            loadW(k1);
            asm volatile("cp.async.wait_group 1;");
        } else {
            asm volatile("cp.async.wait_group 0;");
        }
        __syncthreads();

        // ---- tf32 MMA over the staged chunk ----
        const float* Xw = Xc + warp * 32 * XSTRIDE;
#pragma unroll
        for (int ks = 0; ks < 4; ks++) {
            const int kb = ks * 8;
            unsigned a0[4], a1[4];
            const float* A0 = Xw + kb + t;
            a0[0] = __float_as_uint(A0[g * XSTRIDE]);
            a0[1] = __float_as_uint(A0[(g + 8) * XSTRIDE]);
            a0[2] = __float_as_uint(A0[g * XSTRIDE + 4]);
            a0[3] = __float_as_uint(A0[(g + 8) * XSTRIDE + 4]);
            const float* A1 = A0 + 16 * XSTRIDE;
            a1[0] = __float_as_uint(A1[g * XSTRIDE]);
            a1[1] = __float_as_uint(A1[(g + 8) * XSTRIDE]);
            a1[2] = __float_as_uint(A1[g * XSTRIDE + 4]);
            a1[3] = __float_as_uint(A1[(g + 8) * XSTRIDE + 4]);
#pragma unroll
            for (int nt = 0; nt < 8; nt++) {
                const float* Bp = Wc + (nt * 8 + g) * XSTRIDE + kb + t;
                unsigned b0 = __float_as_uint(Bp[0]);
                unsigned b1 = __float_as_uint(Bp[4]);
                mma_tf32(acc[0][nt], a0, b0, b1);
                mma_tf32(acc[1][nt], a1, b0, b1);
            }
        }
        __syncthreads();
    }

    // ---- bias (only k-half 0 adds it) ----
    if (khalf == 0 && tid < NT) {
        int n = n0 + tid;
        bias_s[tid] = fmaf(softplus_fast(brho[n]), epsb[n], bmu[n]);
    }
    __syncthreads();

    // ---- epilogue: atomic-accumulate partial output ----
#pragma unroll
    for (int mt = 0; mt < 2; mt++) {
        int r0 = warp * 32 + mt * 16 + g;
#pragma unroll
        for (int nt = 0; nt < 8; nt++) {
            int col = n0 + nt * 8 + 2 * t;
            float b0v = 0.f, b1v = 0.f;
            if (khalf == 0) {
                b0v = bias_s[nt * 8 + 2 * t];
                b1v = bias_s[nt * 8 + 2 * t + 1];
            }
            atomicAdd(&out[(long)r0 * OUT_F + col],       acc[mt][nt][0] + b0v);
            atomicAdd(&out[(long)r0 * OUT_F + col + 1],   acc[mt][nt][1] + b1v);
            atomicAdd(&out[(long)(r0 + 8) * OUT_F + col],     acc[mt][nt][2] + b0v);
            atomicAdd(&out[(long)(r0 + 8) * OUT_F + col + 1], acc[mt][nt][3] + b1v);
        }
    }

    // ---- KL reduction ----
#pragma unroll
    for (int o = 16; o; o >>= 1)
        klsum += __shfl_xor_sync(0xFFFFFFFFu, klsum, o);
    if (lane == 0) klred[warp] = klsum;
    __syncthreads();
    if (tid == 0) {
        float s = 0.f;
#pragma unroll
        for (int i = 0; i < 8; i++) s += klred[i];
        atomicAdd(klout, s);
    }
}

// ---------------------------------------------------------------------------
extern "C" void kernel_launch(void* const* d_in, const int* in_sizes, int n_in,
                              void* d_out, int out_size) {
    const float* x    = (const float*)d_in[0];
    const float* wmu  = (const float*)d_in[1];
    const float* wrho = (const float*)d_in[2];
    const float* bmu  = (const float*)d_in[3];
    const float* brho = (const float*)d_in[4];
    const float* epsw = (const float*)d_in[5];
    const float* epsb = (const float*)d_in[6];
    const float* pmu  = (const float*)d_in[7];
    const float* psig = (const float*)d_in[8];
    float* out = (float*)d_out;

    int total = BATCH * IN_F;           // 1048576 x elements to convert
    int n = out_size > total ? out_size : total;
    vl_prep<<<(n + 255) / 256, 256>>>(x, out, out_size);

    cudaFuncSetAttribute(vl_main, cudaFuncAttributeMaxDynamicSharedMemorySize,
                         SMEM_BYTES);
    vl_main<<<OUT_F / NT * KSPLIT, THREADS, SMEM_BYTES>>>(
        wmu, wrho, epsw, pmu, psig, bmu, brho, epsb,
        out, out + (out_size - 1));
}

// round 2
// speedup vs baseline: 1.2586x; 1.2586x over previous
#include <cuda_runtime.h>
#include <cuda_bf16.h>
#include <math.h>

// ---------------------------------------------------------------------------
// VariationalLinear fused kernel, round 2 (sm_100a)
//   out(256,4096) = x @ W^T + b,  W = mu + softplus(rho)*eps_w, + analytic KL
//
// R2 changes vs R1 (176us, latency-bound: occ 12.4%, DRAM 24%):
//  - ALL weight streams via cp.async -> SMEM (no register staging: regs drop,
//    2 CTAs/SM), KC=16 double-buffered pipeline.
//  - bias folded into prep kernel (out initialized to bias, not 0).
//  - grid 256 CTAs (NT=64 x KSPLIT=4), all resident in one wave at 2/SM.
//  - single Wgen buffer (barrier ordering makes double-buffer unnecessary).
// ---------------------------------------------------------------------------

#define BATCH   256
#define IN_F    4096
#define OUT_F   4096
#define NT      64                 // out-features per CTA
#define KSPLIT  4
#define KSEG    (IN_F / KSPLIT)    // 1024
#define KC      16                 // K per pipeline chunk
#define NCHUNK  (KSEG / KC)        // 64
#define XSTRIDE 20                 // padded SMEM row stride (floats)
#define THREADS 256

#define XS_STAGE  (BATCH * XSTRIDE)      // 5120 floats per stage
#define RAW_STAGE (5 * NT * KC)          // 5120 floats per stage (5 streams)
#define WG_SIZE   (NT * XSTRIDE)         // 1280 floats (single buffer)
#define SMEM_FLOATS (2 * XS_STAGE + 2 * RAW_STAGE + WG_SIZE)
#define SMEM_BYTES  (SMEM_FLOATS * 4)    // 87040 B

__device__ __align__(16) float g_x_tf32[BATCH * IN_F];

__device__ __forceinline__ unsigned cvt_tf32(float x) {
    unsigned r;
    asm volatile("cvt.rna.tf32.f32 %0, %1;" : "=r"(r) : "f"(x));
    return r;
}

__device__ __forceinline__ void cp_async16(void* smem_dst, const void* gsrc) {
    unsigned saddr = (unsigned)__cvta_generic_to_shared(smem_dst);
    asm volatile("cp.async.cg.shared.global [%0], [%1], 16;"
                 :: "r"(saddr), "l"(gsrc));
}

__device__ __forceinline__ void mma_tf32(float* c, const unsigned* a,
                                         unsigned b0, unsigned b1) {
    asm volatile(
        "mma.sync.aligned.m16n8k8.row.col.f32.tf32.tf32.f32 "
        "{%0,%1,%2,%3}, {%4,%5,%6,%7}, {%8,%9}, {%0,%1,%2,%3};"
        : "+f"(c[0]), "+f"(c[1]), "+f"(c[2]), "+f"(c[3])
        : "r"(a[0]), "r"(a[1]), "r"(a[2]), "r"(a[3]), "r"(b0), "r"(b1));
}

__device__ __forceinline__ float softplus_fast(float r) {
    return (r > 15.f) ? r : __logf(1.f + __expf(r));
}

// ---------------------------------------------------------------------------
// Prep: out <- bias broadcast (main kernel atomically adds GEMM partials),
// KL slot <- 0, x -> tf32 scratch.
// ---------------------------------------------------------------------------
__global__ void vl_prep(const float* __restrict__ x,
                        const float* __restrict__ bmu,
                        const float* __restrict__ brho,
                        const float* __restrict__ epsb,
                        float* __restrict__ out, int out_size) {
    int i = blockIdx.x * blockDim.x + threadIdx.x;
    if (i < BATCH * OUT_F) {
        int col = i & (OUT_F - 1);
        out[i] = fmaf(softplus_fast(brho[col]), epsb[col], bmu[col]);
    } else if (i < out_size) {
        out[i] = 0.f;   // KL accumulator slot
    }
    if (i < BATCH * IN_F)
        g_x_tf32[i] = __uint_as_float(cvt_tf32(x[i]));
}

// ---------------------------------------------------------------------------
// Main fused kernel
// ---------------------------------------------------------------------------
__global__ void __launch_bounds__(THREADS, 2)
vl_main(const float* __restrict__ mu, const float* __restrict__ rho,
        const float* __restrict__ epsw, const float* __restrict__ pmu,
        const float* __restrict__ psig,
        float* __restrict__ out, float* __restrict__ klout) {
    extern __shared__ float sm[];
    float* Xs   = sm;                         // [2][BATCH][XSTRIDE]
    float* Raw  = sm + 2 * XS_STAGE;          // [2][5][NT*KC]
    float* Wgen = sm + 2 * XS_STAGE + 2 * RAW_STAGE;  // [NT][XSTRIDE]
    __shared__ float klred[8];

    const int tid  = threadIdx.x;
    const int warp = tid >> 5;
    const int lane = tid & 31;
    const int g    = lane >> 2;               // 0..7
    const int t    = lane & 3;                // 0..3

    const int ntile = blockIdx.x >> 2;
    const int kseg  = blockIdx.x & 3;
    const int n0    = ntile * NT;
    const int kbase = kseg * KSEG;

    // warp covers M rows [warp*32, warp*32+32), all NT=64 cols
    float acc[2][8][4];
#pragma unroll
    for (int mt = 0; mt < 2; mt++)
#pragma unroll
        for (int nt = 0; nt < 8; nt++)
#pragma unroll
            for (int i = 0; i < 4; i++) acc[mt][nt][i] = 0.f;

    float klsum = 0.f;

    // W-gen / raw indexing: thread handles 4 consecutive weight elements
    const int wrow = tid >> 2;                // 0..63
    const int wseg = tid & 3;                 // 0..3 (x4 floats)
    const long wg_gofs = (long)(n0 + wrow) * IN_F + kbase + wseg * 4;
    const int  raw_t   = tid * 4;             // float offset within a stream
    const int  wg_sofs = wrow * XSTRIDE + wseg * 4;

    const float* streams[5] = { mu, rho, epsw, pmu, psig };

    auto prefetch = [&](int c) {              // stage chunk c into buffers c&1
        const int st = c & 1;
        const int k0 = c * KC;
        // X tile: 256 rows x 16 cols = 1024 float4, 4 per thread
        float* xd = Xs + st * XS_STAGE;
#pragma unroll
        for (int i = 0; i < 4; i++) {
            int f   = tid + THREADS * i;      // 0..1023
            int row = f >> 2;
            int seg = f & 3;
            cp_async16(xd + row * XSTRIDE + seg * 4,
                       g_x_tf32 + (long)row * IN_F + kbase + k0 + seg * 4);
        }
        // 5 raw weight streams: 256 float4 each, 1 per thread per stream
        float* rd = Raw + st * RAW_STAGE;
#pragma unroll
        for (int s = 0; s < 5; s++) {
            cp_async16(rd + s * (NT * KC) + raw_t,
                       streams[s] + wg_gofs + k0);
        }
    };

    // prologue: stage chunk 0
    prefetch(0);
    asm volatile("cp.async.commit_group;");

    for (int c = 0; c < NCHUNK; c++) {
        const int st = c & 1;
        asm volatile("cp.async.wait_group 0;");
        __syncthreads();   // stage st ready; all threads past chunk c-1

        // ---- prefetch chunk c+1 (overlaps with Wgen + MMA below) ----
        if (c + 1 < NCHUNK) prefetch(c + 1);
        asm volatile("cp.async.commit_group;");

        // ---- generate W tile (tf32) + KL from raw SMEM ----
        {
            const float* rb = Raw + st * RAW_STAGE;
            float4 m4 = *reinterpret_cast<const float4*>(rb + 0 * NT * KC + raw_t);
            float4 r4 = *reinterpret_cast<const float4*>(rb + 1 * NT * KC + raw_t);
            float4 e4 = *reinterpret_cast<const float4*>(rb + 2 * NT * KC + raw_t);
            float4 p4 = *reinterpret_cast<const float4*>(rb + 3 * NT * KC + raw_t);
            float4 s4 = *reinterpret_cast<const float4*>(rb + 4 * NT * KC + raw_t);
            const float mv[4] = {m4.x, m4.y, m4.z, m4.w};
            const float rv[4] = {r4.x, r4.y, r4.z, r4.w};
            const float ev[4] = {e4.x, e4.y, e4.z, e4.w};
            const float pv[4] = {p4.x, p4.y, p4.z, p4.w};
            const float sv[4] = {s4.x, s4.y, s4.z, s4.w};
            float wv[4];
#pragma unroll
            for (int q = 0; q < 4; q++) {
                float sg = softplus_fast(rv[q]);
                float w  = fmaf(sg, ev[q], mv[q]);
                wv[q] = __uint_as_float(cvt_tf32(w));
                float d   = mv[q] - pv[q];
                float ps2 = sv[q] * sv[q];
                klsum += __logf(sv[q]) - __logf(sg)
                       + __fdividef(0.5f * fmaf(sg, sg, d * d), ps2)
                       - 0.5f;
            }
            *reinterpret_cast<float4*>(Wgen + wg_sofs) =
                make_float4(wv[0], wv[1], wv[2], wv[3]);
        }
        __syncthreads();   // Wgen visible

        // ---- tf32 MMA over the chunk ----
        const float* Xc = Xs + st * XS_STAGE + warp * 32 * XSTRIDE;
#pragma unroll
        for (int ks = 0; ks < 2; ks++) {
            const int kb = ks * 8;
            unsigned a0[4], a1[4];
            const float* A0 = Xc + kb + t;
            a0[0] = __float_as_uint(A0[g * XSTRIDE]);
            a0[1] = __float_as_uint(A0[(g + 8) * XSTRIDE]);
            a0[2] = __float_as_uint(A0[g * XSTRIDE + 4]);
            a0[3] = __float_as_uint(A0[(g + 8) * XSTRIDE + 4]);
            const float* A1 = A0 + 16 * XSTRIDE;
            a1[0] = __float_as_uint(A1[g * XSTRIDE]);
            a1[1] = __float_as_uint(A1[(g + 8) * XSTRIDE]);
            a1[2] = __float_as_uint(A1[g * XSTRIDE + 4]);
            a1[3] = __float_as_uint(A1[(g + 8) * XSTRIDE + 4]);
#pragma unroll
            for (int nt = 0; nt < 8; nt++) {
                const float* Bp = Wgen + (nt * 8 + g) * XSTRIDE + kb + t;
                unsigned b0 = __float_as_uint(Bp[0]);
                unsigned b1 = __float_as_uint(Bp[4]);
                mma_tf32(acc[0][nt], a0, b0, b1);
                mma_tf32(acc[1][nt], a1, b0, b1);
            }
        }
        __syncthreads();   // done with Wgen + stage st before next iteration
    }

    // ---- epilogue: atomic-accumulate partial output (bias already in out) ----
#pragma unroll
    for (int mt = 0; mt < 2; mt++) {
        int r0 = warp * 32 + mt * 16 + g;
#pragma unroll
        for (int nt = 0; nt < 8; nt++) {
            int col = n0 + nt * 8 + 2 * t;
            atomicAdd(&out[(long)r0 * OUT_F + col],           acc[mt][nt][0]);
            atomicAdd(&out[(long)r0 * OUT_F + col + 1],       acc[mt][nt][1]);
            atomicAdd(&out[(long)(r0 + 8) * OUT_F + col],     acc[mt][nt][2]);
            atomicAdd(&out[(long)(r0 + 8) * OUT_F + col + 1], acc[mt][nt][3]);
        }
    }

    // ---- KL reduction ----
#pragma unroll
    for (int o = 16; o; o >>= 1)
        klsum += __shfl_xor_sync(0xFFFFFFFFu, klsum, o);
    if (lane == 0) klred[warp] = klsum;
    __syncthreads();
    if (tid == 0) {
        float s = 0.f;
#pragma unroll
        for (int i = 0; i < 8; i++) s += klred[i];
        atomicAdd(klout, s);
    }
}

// ---------------------------------------------------------------------------
extern "C" void kernel_launch(void* const* d_in, const int* in_sizes, int n_in,
                              void* d_out, int out_size) {
    const float* x    = (const float*)d_in[0];
    const float* wmu  = (const float*)d_in[1];
    const float* wrho = (const float*)d_in[2];
    const float* bmu  = (const float*)d_in[3];
    const float* brho = (const float*)d_in[4];
    const float* epsw = (const float*)d_in[5];
    const float* epsb = (const float*)d_in[6];
    const float* pmu  = (const float*)d_in[7];
    const float* psig = (const float*)d_in[8];
    float* out = (float*)d_out;

    int n = BATCH * IN_F;
    if (out_size > n) n = out_size;
    vl_prep<<<(n + 255) / 256, 256>>>(x, bmu, brho, epsb, out, out_size);

    cudaFuncSetAttribute(vl_main, cudaFuncAttributeMaxDynamicSharedMemorySize,
                         SMEM_BYTES);
    vl_main<<<(OUT_F / NT) * KSPLIT, THREADS, SMEM_BYTES>>>(
        wmu, wrho, epsw, pmu, psig, out, out + (out_size - 1));
}